// round 5
// baseline (speedup 1.0000x reference)
#include <cuda_runtime.h>
#include <cstdint>
#include <cstddef>

// Problem constants
#define N_ROWS 16384
#define K_TOT  16384
#define NCOL   128      // fused s+u branch width (2 x 64)
#define BM     128      // M tile per CTA in big GEMM
#define BK     16       // K tile per iteration

// Scratch (device globals: allocation-free rule)
__device__ float g_T[(size_t)N_ROWS * NCOL];  // B operand of big GEMM (tf32-prerounded)
__device__ float g_Y[(size_t)N_ROWS * NCOL];  // big GEMM output (post-elu, fp32)

__device__ __forceinline__ float elu_f(float x) { return x > 0.0f ? x : expm1f(x); }

__device__ __forceinline__ float round_tf32(float x) {
    uint32_t u;
    asm("cvt.rna.tf32.f32 %0, %1;" : "=r"(u) : "f"(x));
    return __uint_as_float(u);
}

// ---------------------------------------------------------------------------
// k_pre: T[:, h*64 + c] = sum_k elu(z[r, h*64+k]) * W0[k][c]   (h = 0,1)
// Output pre-rounded to tf32 so the big GEMM's B operand is exactly representable.
// ---------------------------------------------------------------------------
__global__ void k_pre(const float* __restrict__ z, const float* __restrict__ W) {
    int h = blockIdx.y;
    int row0 = blockIdx.x * 64;
    __shared__ float xs[64][65];
    __shared__ float ws[64][65];
    int tid = threadIdx.x;
    for (int i = tid; i < 4096; i += 256) {
        int r = i >> 6, c = i & 63;
        xs[r][c] = elu_f(z[(size_t)(row0 + r) * 192 + h * 64 + c]);
        ws[r][c] = W[r * 64 + c];
    }
    __syncthreads();
    int tr = (tid >> 4) << 2, tc = (tid & 15) << 2;
    float acc[4][4] = {};
#pragma unroll 8
    for (int k = 0; k < 64; k++) {
        float xv[4], wv[4];
#pragma unroll
        for (int i = 0; i < 4; i++) xv[i] = xs[tr + i][k];
#pragma unroll
        for (int j = 0; j < 4; j++) wv[j] = ws[k][tc + j];
#pragma unroll
        for (int i = 0; i < 4; i++)
#pragma unroll
            for (int j = 0; j < 4; j++) acc[i][j] += xv[i] * wv[j];
    }
#pragma unroll
    for (int i = 0; i < 4; i++)
#pragma unroll
        for (int j = 0; j < 4; j++)
            g_T[(size_t)(row0 + tr + i) * NCOL + h * 64 + tc + j] = round_tf32(acc[i][j]);
}

// ---------------------------------------------------------------------------
// k_mid: T[:, h*64 + c] = sum_k Y[r, h*64+k] * W1[k][c]   (input already elu'd)
// ---------------------------------------------------------------------------
__global__ void k_mid(const float* __restrict__ W) {
    int h = blockIdx.y;
    int row0 = blockIdx.x * 64;
    __shared__ float xs[64][65];
    __shared__ float ws[64][65];
    int tid = threadIdx.x;
    for (int i = tid; i < 4096; i += 256) {
        int r = i >> 6, c = i & 63;
        xs[r][c] = g_Y[(size_t)(row0 + r) * NCOL + h * 64 + c];
        ws[r][c] = W[r * 64 + c];
    }
    __syncthreads();
    int tr = (tid >> 4) << 2, tc = (tid & 15) << 2;
    float acc[4][4] = {};
#pragma unroll 8
    for (int k = 0; k < 64; k++) {
        float xv[4], wv[4];
#pragma unroll
        for (int i = 0; i < 4; i++) xv[i] = xs[tr + i][k];
#pragma unroll
        for (int j = 0; j < 4; j++) wv[j] = ws[k][tc + j];
#pragma unroll
        for (int i = 0; i < 4; i++)
#pragma unroll
            for (int j = 0; j < 4; j++) acc[i][j] += xv[i] * wv[j];
    }
#pragma unroll
    for (int i = 0; i < 4; i++)
#pragma unroll
        for (int j = 0; j < 4; j++)
            g_T[(size_t)(row0 + tr + i) * NCOL + h * 64 + tc + j] = round_tf32(acc[i][j]);
}

// ---------------------------------------------------------------------------
// k_big: Y = elu(adj @ T + bias)   M=16384, N=128, K=16384
// 128 CTAs, 256 threads (8 warps as 4x2), tf32 mma.sync m16n8k8,
// cp.async double-buffered K pipeline (BK=16).
// ---------------------------------------------------------------------------
__global__ void __launch_bounds__(256, 1) k_big(const float* __restrict__ adj,
                                                const float* __restrict__ bias) {
    __shared__ float sA[2][BM][20];    // 128 rows x 16 k (+4 pad -> conflict-free frag loads)
    __shared__ float sB[2][BK][132];   // 16 k x 128 cols (+4 pad)

    int tid = threadIdx.x;
    int lane = tid & 31, wid = tid >> 5;
    int wm = wid & 3, wn = wid >> 2;          // 4 (M) x 2 (N) warps
    size_t m0 = (size_t)blockIdx.x * BM;

    uint32_t sA_base, sB_base;
    asm("{ .reg .u64 t; cvta.to.shared.u64 t, %1; cvt.u32.u64 %0, t; }"
        : "=r"(sA_base) : "l"(&sA[0][0][0]));
    asm("{ .reg .u64 t; cvta.to.shared.u64 t, %1; cvt.u32.u64 %0, t; }"
        : "=r"(sB_base) : "l"(&sB[0][0][0]));

    auto prefetch = [&](int buf, int kt) {
        int k0 = kt * BK;
#pragma unroll
        for (int i = 0; i < 2; i++) {                    // A: 128x16 = 512 float4
            int s = i * 256 + tid;
            int r = s >> 2, kq = (s & 3) << 2;
            const float* src = adj + (m0 + r) * (size_t)K_TOT + k0 + kq;
            uint32_t dst = sA_base + (uint32_t)(((buf * BM + r) * 20 + kq) * 4);
            asm volatile("cp.async.ca.shared.global [%0], [%1], 16;" :: "r"(dst), "l"(src));
        }
#pragma unroll
        for (int i = 0; i < 2; i++) {                    // B: 16x128 = 512 float4
            int s = i * 256 + tid;
            int r = s >> 5, cq = (s & 31) << 2;
            const float* src = g_T + (size_t)(k0 + r) * NCOL + cq;
            uint32_t dst = sB_base + (uint32_t)(((buf * BK + r) * 132 + cq) * 4);
            asm volatile("cp.async.ca.shared.global [%0], [%1], 16;" :: "r"(dst), "l"(src));
        }
    };

    float acc[2][8][4];
#pragma unroll
    for (int t = 0; t < 2; t++)
#pragma unroll
        for (int j = 0; j < 8; j++)
#pragma unroll
            for (int q = 0; q < 4; q++) acc[t][j][q] = 0.0f;

    prefetch(0, 0);
    asm volatile("cp.async.commit_group;");

    const int KT = K_TOT / BK;   // 1024
    for (int kt = 0; kt < KT; kt++) {
        int buf = kt & 1;
        if (kt + 1 < KT) {
            prefetch(buf ^ 1, kt + 1);
            asm volatile("cp.async.commit_group;");
            asm volatile("cp.async.wait_group 1;");
        } else {
            asm volatile("cp.async.wait_group 0;");
        }
        __syncthreads();

#pragma unroll
        for (int kk = 0; kk < 2; kk++) {
            int kb = kk * 8;
            uint32_t a[2][4];
#pragma unroll
            for (int t = 0; t < 2; t++) {
                int r = wm * 32 + t * 16 + (lane >> 2);
                int kc = kb + (lane & 3);
                // round-to-nearest tf32: kills coherent truncation bias over K=16384
                a[t][0] = __float_as_uint(round_tf32(sA[buf][r][kc]));
                a[t][1] = __float_as_uint(round_tf32(sA[buf][r + 8][kc]));
                a[t][2] = __float_as_uint(round_tf32(sA[buf][r][kc + 4]));
                a[t][3] = __float_as_uint(round_tf32(sA[buf][r + 8][kc + 4]));
            }
#pragma unroll
            for (int j = 0; j < 8; j++) {
                int c = wn * 64 + j * 8 + (lane >> 2);
                int k1 = kb + (lane & 3);
                uint32_t b0 = __float_as_uint(sB[buf][k1][c]);       // B pre-rounded in k_pre/k_mid
                uint32_t b1 = __float_as_uint(sB[buf][k1 + 4][c]);
#pragma unroll
                for (int t = 0; t < 2; t++) {
                    asm volatile(
                        "mma.sync.aligned.m16n8k8.row.col.f32.tf32.tf32.f32 "
                        "{%0,%1,%2,%3}, {%4,%5,%6,%7}, {%8,%9}, {%0,%1,%2,%3};"
                        : "+f"(acc[t][j][0]), "+f"(acc[t][j][1]),
                          "+f"(acc[t][j][2]), "+f"(acc[t][j][3])
                        : "r"(a[t][0]), "r"(a[t][1]), "r"(a[t][2]), "r"(a[t][3]),
                          "r"(b0), "r"(b1));
                }
            }
        }
        __syncthreads();
    }

    // Epilogue: + bias (broadcast per 64), elu, store fp32
#pragma unroll
    for (int t = 0; t < 2; t++) {
#pragma unroll
        for (int j = 0; j < 8; j++) {
            int r = (int)m0 + wm * 32 + t * 16 + (lane >> 2);
            int c = wn * 64 + j * 8 + ((lane & 3) << 1);
            float b0 = bias[c & 63];
            float b1 = bias[(c + 1) & 63];
            g_Y[(size_t)r * NCOL + c]           = elu_f(acc[t][j][0] + b0);
            g_Y[(size_t)r * NCOL + c + 1]       = elu_f(acc[t][j][1] + b1);
            g_Y[(size_t)(r + 8) * NCOL + c]     = elu_f(acc[t][j][2] + b0);
            g_Y[(size_t)(r + 8) * NCOL + c + 1] = elu_f(acc[t][j][3] + b1);
        }
    }
}

// ---------------------------------------------------------------------------
// k_final: out = [Y2_s | Y2_u | z_a] @ Wl + bl    (K = 192 in 3 chunks of 64)
// ---------------------------------------------------------------------------
__global__ void k_final(const float* __restrict__ z, const float* __restrict__ Wl,
                        const float* __restrict__ bl, float* __restrict__ out) {
    int row0 = blockIdx.x * 64;
    __shared__ float xs[64][65];
    __shared__ float ws[64][65];
    int tid = threadIdx.x;
    int tr = (tid >> 4) << 2, tc = (tid & 15) << 2;
    float acc[4][4] = {};
    for (int ch = 0; ch < 3; ch++) {
        __syncthreads();
        for (int i = tid; i < 4096; i += 256) {
            int r = i >> 6, c = i & 63;
            xs[r][c] = (ch < 2) ? g_Y[(size_t)(row0 + r) * NCOL + ch * 64 + c]
                                : z[(size_t)(row0 + r) * 192 + 128 + c];
            ws[r][c] = Wl[(ch * 64 + r) * 64 + c];
        }
        __syncthreads();
#pragma unroll 8
        for (int k = 0; k < 64; k++) {
            float xv[4], wv[4];
#pragma unroll
            for (int i = 0; i < 4; i++) xv[i] = xs[tr + i][k];
#pragma unroll
            for (int j = 0; j < 4; j++) wv[j] = ws[k][tc + j];
#pragma unroll
            for (int i = 0; i < 4; i++)
#pragma unroll
                for (int j = 0; j < 4; j++) acc[i][j] += xv[i] * wv[j];
        }
    }
#pragma unroll
    for (int i = 0; i < 4; i++)
#pragma unroll
        for (int j = 0; j < 4; j++)
            out[(size_t)(row0 + tr + i) * 64 + tc + j] = acc[i][j] + bl[tc + j];
}

// ---------------------------------------------------------------------------
extern "C" void kernel_launch(void* const* d_in, const int* in_sizes, int n_in,
                              void* d_out, int out_size) {
    // Resolve inputs by element count (all sizes distinct; robust to ordering).
    const float *z = nullptr, *adj = nullptr, *Ws = nullptr, *bs = nullptr,
                *Wl = nullptr, *bl = nullptr;
    for (int i = 0; i < n_in; i++) {
        switch (in_sizes[i]) {
            case 16384 * 192:  z   = (const float*)d_in[i]; break;  // 3145728
            case 268435456:    adj = (const float*)d_in[i]; break;  // 16384^2
            case 8192:         Ws  = (const float*)d_in[i]; break;  // 2x64x64
            case 128:          bs  = (const float*)d_in[i]; break;  // 2x64
            case 12288:        Wl  = (const float*)d_in[i]; break;  // 192x64
            case 64:           bl  = (const float*)d_in[i]; break;
            default: break;
        }
    }
    float* out = (float*)d_out;

    // Layer 1 (s+u fused into 128 cols)
    k_pre<<<dim3(256, 2), 256>>>(z, Ws);            // T = elu(z_su) @ W0
    k_big<<<128, 256>>>(adj, bs);                   // Y = elu(adj@T + b0)
    // Layer 2
    k_mid<<<dim3(256, 2), 256>>>(Ws + 4096);        // T = Y @ W1
    k_big<<<128, 256>>>(adj, bs + 64);              // Y = elu(adj@T + b1)
    // Final linear
    k_final<<<256, 256>>>(z, Wl, bl, out);
}